// round 1
// baseline (speedup 1.0000x reference)
#include <cuda_runtime.h>

#define BB 8
#define NN 16384
#define DD 768
#define CC 8
#define NCLS 2
#define D4 (DD/4)                 // 192
#define ROWS_PER_BLOCK 128
#define BLOCKS_PER_BAG (NN/ROWS_PER_BLOCK)   // 128
#define NSEG (BB*CC)              // 64

// Scratch (device globals: allocation-free per harness rules)
__device__ float g_sums[NSEG * DD];
__device__ int   g_counts[NSEG];

__global__ void zero_kernel() {
    int i = blockIdx.x * blockDim.x + threadIdx.x;
    if (i < NSEG * DD) g_sums[i] = 0.0f;
    if (i < NSEG) g_counts[i] = 0;
}

__global__ __launch_bounds__(192)
void seg_sum_kernel(const float* __restrict__ inst, const int* __restrict__ labels) {
    __shared__ float4 s_acc[CC * D4];          // 24 KB per-block accumulator
    __shared__ int s_lbl[ROWS_PER_BLOCK];
    __shared__ int s_cnt[CC];

    const int t   = threadIdx.x;               // 0..191, owns float4 column t
    const int blk = blockIdx.x;
    const int bag   = blk / BLOCKS_PER_BAG;
    const int chunk = blk % BLOCKS_PER_BAG;
    const long row0 = (long)bag * NN + (long)chunk * ROWS_PER_BLOCK;

    for (int i = t; i < CC * D4; i += 192) s_acc[i] = make_float4(0.f, 0.f, 0.f, 0.f);
    if (t < CC) s_cnt[t] = 0;
    __syncthreads();

    if (t < ROWS_PER_BLOCK) {
        int l = labels[row0 + t];
        s_lbl[t] = l;
        atomicAdd(&s_cnt[l], 1);
    }
    __syncthreads();

    const float4* __restrict__ base =
        reinterpret_cast<const float4*>(inst) + row0 * D4;

    #pragma unroll 4
    for (int r = 0; r < ROWS_PER_BLOCK; ++r) {
        float4 v = base[(long)r * D4 + t];     // coalesced LDG.128
        int l = s_lbl[r];
        float4* a = &s_acc[l * D4 + t];        // conflict-free 128b smem RMW
        a->x += v.x; a->y += v.y; a->z += v.z; a->w += v.w;
    }
    __syncthreads();

    // Flush block-partial sums to global
    for (int i = t; i < CC * D4; i += 192) {
        float4 v = s_acc[i];
        int c = i / D4;
        int d = (i % D4) * 4;
        float* p = &g_sums[(bag * CC + c) * DD + d];
        atomicAdd(p + 0, v.x);
        atomicAdd(p + 1, v.y);
        atomicAdd(p + 2, v.z);
        atomicAdd(p + 3, v.w);
    }
    if (t < CC) atomicAdd(&g_counts[bag * CC + t], s_cnt[t]);
}

__global__ __launch_bounds__(256)
void finalize_kernel(const float* __restrict__ head_w,
                     const float* __restrict__ head_b,
                     float* __restrict__ out) {
    __shared__ float s_logits[NSEG][NCLS];
    const int t = threadIdx.x;
    const int warp = t >> 5, lane = t & 31;

    // 128 dot products (64 segments x 2 classes), one per warp iteration
    for (int i = warp; i < NSEG * NCLS; i += 8) {
        int seg = i / NCLS, c = i % NCLS;
        int cnt = g_counts[seg];
        float inv = 1.0f / (float)(cnt > 0 ? cnt : 1);
        float acc = 0.0f;
        for (int d = lane; d < DD; d += 32)
            acc += g_sums[seg * DD + d] * head_w[c * DD + d];
        #pragma unroll
        for (int o = 16; o > 0; o >>= 1)
            acc += __shfl_xor_sync(0xffffffff, acc, o);
        if (lane == 0)
            s_logits[seg][c] = acc * inv + head_b[c];   // (sum/cnt)@W + b
    }
    __syncthreads();

    if (t < BB) {
        float best = -1e30f; int bestc = 0;
        #pragma unroll
        for (int c8 = 0; c8 < CC; ++c8) {
            float l0 = s_logits[t * CC + c8][0];
            float l1 = s_logits[t * CC + c8][1];
            float m  = fmaxf(l0, l1);
            float e0 = expf(l0 - m), e1 = expf(l1 - m);
            float score = 1.0f - e0 / (e0 + e1);        // 1 - p[nor_index=0]
            if (score > best) { best = score; bestc = c8; }
        }
        out[t * NCLS + 0] = s_logits[t * CC + bestc][0];
        out[t * NCLS + 1] = s_logits[t * CC + bestc][1];
    }
}

extern "C" void kernel_launch(void* const* d_in, const int* in_sizes, int n_in,
                              void* d_out, int out_size) {
    const float* inst_feat = (const float*)d_in[0];   // [B, N, D] f32
    const int*   labels    = (const int*)  d_in[1];   // [B, N] i32
    const float* head_w    = (const float*)d_in[2];   // [NC, D] f32
    const float* head_b    = (const float*)d_in[3];   // [NC] f32
    float* out = (float*)d_out;                       // [B, NC] f32

    zero_kernel<<<(NSEG * DD + 255) / 256, 256>>>();
    seg_sum_kernel<<<BB * BLOCKS_PER_BAG, 192>>>(inst_feat, labels);
    finalize_kernel<<<1, 256>>>(head_w, head_b, out);
}